// round 5
// baseline (speedup 1.0000x reference)
#include <cuda_runtime.h>
#include <stdint.h>

#define DD 128
#define NMAX 50176
#define EMAX 819200

// ---------------- scratch (static device globals; no allocation) ------------
__device__ int   g_cnt   [NMAX];        // in-degree counts (excl self loop)
__device__ int   g_cnt2  [NMAX];        // csr fill cursors
__device__ int   g_rowptr[NMAX + 1];    // CSR row offsets
__device__ int   g_csr   [EMAX];        // CSR src indices
__device__ int   g_bsum  [256];         // scan block sums
__device__ int   g_boff  [256];         // scan block offsets
__device__ float g_dis   [NMAX];        // 1/sqrt(deg)
__device__ float g_hw    [NMAX * DD];   // x@W1, then h1@W2
__device__ float g_agg   [NMAX * DD];   // conv1 output (pre-BN)
__device__ float g_bn    [2 * DD];      // col sums / sumsq
__device__ float g_sA    [DD];          // gamma*rstd
__device__ float g_sB    [DD];          // beta - mu*gamma*rstd

// ---------------- in-degree histogram over dst -------------------------------
__global__ void k_deg(const int* __restrict__ dst, int E) {
    int e = blockIdx.x * blockDim.x + threadIdx.x;
    if (e < E) atomicAdd(&g_cnt[dst[e]], 1);
}

// ---------------- scan phase 1: per-block exclusive scan + block sum + dis ---
__global__ void __launch_bounds__(256) k_scan1(int n) {
    __shared__ int s[256];
    int t = threadIdx.x;
    int i = blockIdx.x * 256 + t;
    int v = (i < n) ? g_cnt[i] : 0;
    if (i < n) g_dis[i] = rsqrtf((float)(1 + v));   // fused dis
    s[t] = v;
    __syncthreads();
#pragma unroll
    for (int off = 1; off < 256; off <<= 1) {
        int u = (t >= off) ? s[t - off] : 0;
        __syncthreads();
        s[t] += u;
        __syncthreads();
    }
    if (i <= n) g_rowptr[i] = s[t] - v;   // exclusive within block
    if (t == 255) g_bsum[blockIdx.x] = s[255];
}

// ---------------- scan phase 2: scan block sums (<=256 blocks) ---------------
__global__ void __launch_bounds__(256) k_scan2(int nb, int n) {
    __shared__ int s[256];
    int t = threadIdx.x;
    int v = (t < nb) ? g_bsum[t] : 0;
    s[t] = v;
    __syncthreads();
#pragma unroll
    for (int off = 1; off < 256; off <<= 1) {
        int u = (t >= off) ? s[t - off] : 0;
        __syncthreads();
        s[t] += u;
        __syncthreads();
    }
    if (t < nb) g_boff[t] = s[t] - v;     // exclusive block offsets
    if (t == 255) g_rowptr[n] = s[255];   // total
}

// ---------------- scan phase 3: add block offsets -----------------------------
__global__ void __launch_bounds__(256) k_scan3(int n) {
    int i = blockIdx.x * 256 + threadIdx.x;
    if (i < n) g_rowptr[i] += g_boff[blockIdx.x];
}

// ---------------- CSR fill: slot per (dst, in-edge) ---------------------------
__global__ void k_fill(const int* __restrict__ src,
                       const int* __restrict__ dst, int E) {
    int e = blockIdx.x * blockDim.x + threadIdx.x;
    if (e >= E) return;
    int d = dst[e];
    int pos = g_rowptr[d] + atomicAdd(&g_cnt2[d], 1);
    g_csr[pos] = src[e];
}

// ---------------- GEMM: C[n,128] = A'[n,128] @ W[128,128] --------------------
#define SMEM_GEMM ((64 * 128 + 128 * 34) * 4)

__device__ __forceinline__ unsigned long long fma2(unsigned long long a,
                                                   unsigned long long b,
                                                   unsigned long long c) {
    unsigned long long d;
    asm("fma.rn.f32x2 %0, %1, %2, %3;" : "=l"(d) : "l"(a), "l"(b), "l"(c));
    return d;
}

__global__ void __launch_bounds__(256) k_gemm(const float* __restrict__ A,
                                              const float* __restrict__ W,
                                              float* __restrict__ C, int n,
                                              int fuseBN) {
    extern __shared__ float sm[];
    float* sX  = sm;                 // [64][128]
    float* sWt = sm + 64 * 128;      // [128][34]
    const int tid  = threadIdx.x;
    const int lane = tid & 31;
    const int rg   = tid >> 5;
    const int row0 = blockIdx.x * 64;

    const float4* A4 = (const float4*)A;
#pragma unroll
    for (int i = 0; i < 8; i++) {
        int idx = tid + i * 256;
        int r = idx >> 5, c = idx & 31;
        int gr = row0 + r;
        float4 v = (gr < n) ? A4[(size_t)gr * 32 + c]
                            : make_float4(0.f, 0.f, 0.f, 0.f);
        if (fuseBN) {
            float4 sa = ((const float4*)g_sA)[c];
            float4 sb = ((const float4*)g_sB)[c];
            v.x = fmaxf(fmaf(v.x, sa.x, sb.x), 0.f);
            v.y = fmaxf(fmaf(v.y, sa.y, sb.y), 0.f);
            v.z = fmaxf(fmaf(v.z, sa.z, sb.z), 0.f);
            v.w = fmaxf(fmaf(v.w, sa.w, sb.w), 0.f);
        }
        *(float4*)&sX[r * 128 + c * 4] = v;
    }

    unsigned long long acc[8][4];
#pragma unroll
    for (int j = 0; j < 8; j++)
#pragma unroll
        for (int c = 0; c < 4; c++) acc[j][c] = 0ull;

    for (int kc = 0; kc < 4; kc++) {
        __syncthreads();
#pragma unroll
        for (int i = 0; i < 4; i++) {
            int idx = tid + i * 256;
            int r  = idx & 31;
            int c4 = idx >> 5;
            float4 w = ((const float4*)W)[(size_t)(kc * 32 + r) * 32 + c4];
            sWt[(c4 * 4 + 0) * 34 + r] = w.x;
            sWt[(c4 * 4 + 1) * 34 + r] = w.y;
            sWt[(c4 * 4 + 2) * 34 + r] = w.z;
            sWt[(c4 * 4 + 3) * 34 + r] = w.w;
        }
        __syncthreads();
#pragma unroll 4
        for (int kk = 0; kk < 32; kk += 2) {
            unsigned long long x2[8], w2[4];
#pragma unroll
            for (int j = 0; j < 8; j++)
                x2[j] = *(const unsigned long long*)&sX[(rg * 8 + j) * 128 + kc * 32 + kk];
#pragma unroll
            for (int c = 0; c < 4; c++)
                w2[c] = *(const unsigned long long*)&sWt[(lane + 32 * c) * 34 + kk];
#pragma unroll
            for (int j = 0; j < 8; j++)
#pragma unroll
                for (int c = 0; c < 4; c++)
                    acc[j][c] = fma2(x2[j], w2[c], acc[j][c]);
        }
    }

#pragma unroll
    for (int j = 0; j < 8; j++) {
        int gr = row0 + rg * 8 + j;
        if (gr < n) {
#pragma unroll
            for (int c = 0; c < 4; c++) {
                float lo = __uint_as_float((unsigned)(acc[j][c] & 0xffffffffull));
                float hi = __uint_as_float((unsigned)(acc[j][c] >> 32));
                C[(size_t)gr * DD + lane + 32 * c] = lo + hi;
            }
        }
    }
}

// ---------------- CSR gather, one warp per dst node; optional fused BN stats -
__global__ void __launch_bounds__(256) k_gather(const float* __restrict__ hw,
                                                const float* __restrict__ bias,
                                                const float* __restrict__ agg,
                                                float* __restrict__ outbuf,
                                                int n, int skip, int dobn) {
    __shared__ float sbn[2 * DD];   // [0:128) col sums, [128:256) col sumsq
    if (dobn) sbn[threadIdx.x] = 0.0f;

    int d = (blockIdx.x * blockDim.x + threadIdx.x) >> 5;
    int lane = threadIdx.x & 31;
    bool valid = d < n;

    float4 acc = make_float4(0.f, 0.f, 0.f, 0.f);
    if (valid) {
        const float4* hw4 = (const float4*)hw;
        float invd = g_dis[d];
        float sw = invd * invd;

        acc = ((const float4*)bias)[lane];
        float4 hd = hw4[(size_t)d * 32 + lane];
        acc.x = fmaf(hd.x, sw, acc.x);
        acc.y = fmaf(hd.y, sw, acc.y);
        acc.z = fmaf(hd.z, sw, acc.z);
        acc.w = fmaf(hd.w, sw, acc.w);
        if (skip) {
            float4 a  = ((const float4*)agg)[(size_t)d * 32 + lane];
            float4 sa = ((const float4*)g_sA)[lane];
            float4 sb = ((const float4*)g_sB)[lane];
            acc.x += fmaxf(fmaf(a.x, sa.x, sb.x), 0.f);
            acc.y += fmaxf(fmaf(a.y, sa.y, sb.y), 0.f);
            acc.z += fmaxf(fmaf(a.z, sa.z, sb.z), 0.f);
            acc.w += fmaxf(fmaf(a.w, sa.w, sb.w), 0.f);
        }

        int j   = g_rowptr[d];
        int end = g_rowptr[d + 1];
        const float4* hwp = hw4;
        for (; j + 3 < end; j += 4) {
            int s0 = g_csr[j],     s1 = g_csr[j + 1];
            int s2 = g_csr[j + 2], s3 = g_csr[j + 3];
            float w0 = g_dis[s0] * invd, w1 = g_dis[s1] * invd;
            float w2 = g_dis[s2] * invd, w3 = g_dis[s3] * invd;
            float4 v0 = hwp[(size_t)s0 * 32 + lane];
            float4 v1 = hwp[(size_t)s1 * 32 + lane];
            float4 v2 = hwp[(size_t)s2 * 32 + lane];
            float4 v3 = hwp[(size_t)s3 * 32 + lane];
            acc.x = fmaf(v0.x, w0, fmaf(v1.x, w1, fmaf(v2.x, w2, fmaf(v3.x, w3, acc.x))));
            acc.y = fmaf(v0.y, w0, fmaf(v1.y, w1, fmaf(v2.y, w2, fmaf(v3.y, w3, acc.y))));
            acc.z = fmaf(v0.z, w0, fmaf(v1.z, w1, fmaf(v2.z, w2, fmaf(v3.z, w3, acc.z))));
            acc.w = fmaf(v0.w, w0, fmaf(v1.w, w1, fmaf(v2.w, w2, fmaf(v3.w, w3, acc.w))));
        }
        for (; j < end; ++j) {
            int s = g_csr[j];
            float w = g_dis[s] * invd;
            float4 v = hwp[(size_t)s * 32 + lane];
            acc.x = fmaf(v.x, w, acc.x);
            acc.y = fmaf(v.y, w, acc.y);
            acc.z = fmaf(v.z, w, acc.z);
            acc.w = fmaf(v.w, w, acc.w);
        }
        ((float4*)outbuf)[(size_t)d * 32 + lane] = acc;
    }

    if (dobn) {
        __syncthreads();
        if (valid) {
            atomicAdd(&sbn[lane * 4 + 0], acc.x);
            atomicAdd(&sbn[lane * 4 + 1], acc.y);
            atomicAdd(&sbn[lane * 4 + 2], acc.z);
            atomicAdd(&sbn[lane * 4 + 3], acc.w);
            atomicAdd(&sbn[DD + lane * 4 + 0], acc.x * acc.x);
            atomicAdd(&sbn[DD + lane * 4 + 1], acc.y * acc.y);
            atomicAdd(&sbn[DD + lane * 4 + 2], acc.z * acc.z);
            atomicAdd(&sbn[DD + lane * 4 + 3], acc.w * acc.w);
        }
        __syncthreads();
        atomicAdd(&g_bn[threadIdx.x], sbn[threadIdx.x]);
    }
}

__global__ void k_bnfinal(const float* __restrict__ gamma,
                          const float* __restrict__ beta, float inv_n) {
    int c = threadIdx.x;
    float mu = g_bn[c] * inv_n;
    float var = g_bn[DD + c] * inv_n - mu * mu;
    float rstd = rsqrtf(var + 1e-5f);
    float a = gamma[c] * rstd;
    g_sA[c] = a;
    g_sB[c] = beta[c] - mu * a;
}

// ============================================================================
extern "C" void kernel_launch(void* const* d_in, const int* in_sizes, int n_in,
                              void* d_out, int out_size) {
    const float* x     = (const float*)d_in[0];
    const int*   ei    = (const int*)d_in[1];     // int32 edge_index
    const float* W1    = (const float*)d_in[2];
    const float* b1    = (const float*)d_in[3];
    const float* W2    = (const float*)d_in[4];
    const float* b2    = (const float*)d_in[5];
    const float* gamma = (const float*)d_in[6];
    const float* beta  = (const float*)d_in[7];
    float*       out   = (float*)d_out;

    const int n = in_sizes[0] / DD;
    const int E = in_sizes[1] / 2;
    const int* src = ei;
    const int* dst = ei + E;

    static int inited = 0;
    static cudaStream_t s2;
    static cudaEvent_t evFork, evJoin;
    static void *p_cnt, *p_cnt2, *p_bn, *p_hw, *p_agg;
    if (!inited) {
        cudaFuncSetAttribute(k_gemm, cudaFuncAttributeMaxDynamicSharedMemorySize,
                             SMEM_GEMM);
        cudaStreamCreateWithFlags(&s2, cudaStreamNonBlocking);
        cudaEventCreateWithFlags(&evFork, cudaEventDisableTiming);
        cudaEventCreateWithFlags(&evJoin, cudaEventDisableTiming);
        cudaGetSymbolAddress(&p_cnt,  g_cnt);
        cudaGetSymbolAddress(&p_cnt2, g_cnt2);
        cudaGetSymbolAddress(&p_bn,   g_bn);
        cudaGetSymbolAddress(&p_hw,   g_hw);
        cudaGetSymbolAddress(&p_agg,  g_agg);
        inited = 1;
    }
    float* hw  = (float*)p_hw;
    float* agg = (float*)p_agg;

    const int TB = 256;
    const int n_grid    = (n + TB - 1) / TB;
    const int e_grid    = (E + TB - 1) / TB;
    const int gemm_grid = (n + 63) / 64;
    const int gat_grid  = (n * 32 + TB - 1) / TB;   // warp per node

    // ---- fork: CSR build on s2, overlapped with GEMM1 on the main stream ----
    cudaEventRecord(evFork, 0);
    cudaStreamWaitEvent(s2, evFork, 0);
    cudaMemsetAsync(p_cnt,  0, (size_t)n * 4, s2);
    cudaMemsetAsync(p_cnt2, 0, (size_t)n * 4, s2);
    cudaMemsetAsync(p_bn,   0, 2 * DD * 4, s2);
    k_deg  <<<e_grid, TB, 0, s2>>>(dst, E);
    k_scan1<<<n_grid, TB, 0, s2>>>(n);
    k_scan2<<<1,      TB, 0, s2>>>(n_grid, n);
    k_scan3<<<n_grid, TB, 0, s2>>>(n);
    k_fill <<<e_grid, TB, 0, s2>>>(src, dst, E);
    cudaEventRecord(evJoin, s2);

    // ---- layer 1 (main stream) ----
    k_gemm<<<gemm_grid, TB, SMEM_GEMM>>>(x, W1, hw, n, 0);
    cudaStreamWaitEvent(0, evJoin, 0);   // join CSR before gather
    k_gather<<<gat_grid, TB>>>(hw, b1, nullptr, agg, n, 0, 1);
    k_bnfinal<<<1, DD>>>(gamma, beta, 1.0f / (float)n);

    // ---- layer 2: conv on relu(BN(agg)) on the fly; out = h1 + h2 ----
    k_gemm<<<gemm_grid, TB, SMEM_GEMM>>>(agg, W2, hw, n, 1);
    k_gather<<<gat_grid, TB>>>(hw, b2, agg, out, n, 1, 0);
}

// round 6
// speedup vs baseline: 1.2020x; 1.2020x over previous
#include <cuda_runtime.h>
#include <stdint.h>

#define DD 128
#define NMAX 50176
#define EMAX 819200

// ---------------- scratch (static device globals; no allocation) ------------
__device__ int   g_cnt   [NMAX];        // in-degree counts (excl self loop)
__device__ int   g_cnt2  [NMAX];        // csr fill cursors
__device__ int   g_rowptr[NMAX + 1];    // CSR row offsets
__device__ int   g_csr   [EMAX];        // CSR src indices
__device__ int   g_bsum  [256];         // scan block sums
__device__ int   g_boff  [256];         // scan block offsets
__device__ float g_dis   [NMAX];        // 1/sqrt(deg)
__device__ float g_hw    [NMAX * DD];   // x@W1, then h1@W2
__device__ float g_agg   [NMAX * DD];   // conv1 output (pre-BN)
__device__ float g_bn    [2 * DD];      // col sums / sumsq
__device__ float g_sA    [DD];          // gamma*rstd
__device__ float g_sB    [DD];          // beta - mu*gamma*rstd

// ---------------- in-degree histogram over dst -------------------------------
__global__ void k_deg(const int* __restrict__ dst, int E) {
    int e = blockIdx.x * blockDim.x + threadIdx.x;
    if (e < E) atomicAdd(&g_cnt[dst[e]], 1);
}

// ---------------- scan phase 1: per-block exclusive scan + block sum + dis ---
__global__ void __launch_bounds__(256) k_scan1(int n) {
    __shared__ int s[256];
    int t = threadIdx.x;
    int i = blockIdx.x * 256 + t;
    int v = (i < n) ? g_cnt[i] : 0;
    if (i < n) g_dis[i] = rsqrtf((float)(1 + v));   // fused dis
    s[t] = v;
    __syncthreads();
#pragma unroll
    for (int off = 1; off < 256; off <<= 1) {
        int u = (t >= off) ? s[t - off] : 0;
        __syncthreads();
        s[t] += u;
        __syncthreads();
    }
    if (i <= n) g_rowptr[i] = s[t] - v;   // exclusive within block
    if (t == 255) g_bsum[blockIdx.x] = s[255];
}

// ---------------- scan phase 2: scan block sums (<=256 blocks) ---------------
__global__ void __launch_bounds__(256) k_scan2(int nb, int n) {
    __shared__ int s[256];
    int t = threadIdx.x;
    int v = (t < nb) ? g_bsum[t] : 0;
    s[t] = v;
    __syncthreads();
#pragma unroll
    for (int off = 1; off < 256; off <<= 1) {
        int u = (t >= off) ? s[t - off] : 0;
        __syncthreads();
        s[t] += u;
        __syncthreads();
    }
    if (t < nb) g_boff[t] = s[t] - v;     // exclusive block offsets
    if (t == 255) g_rowptr[n] = s[255];   // total
}

// ---------------- scan phase 3: add block offsets -----------------------------
__global__ void __launch_bounds__(256) k_scan3(int n) {
    int i = blockIdx.x * 256 + threadIdx.x;
    if (i < n) g_rowptr[i] += g_boff[blockIdx.x];
}

// ---------------- CSR fill: slot per (dst, in-edge) ---------------------------
__global__ void k_fill(const int* __restrict__ src,
                       const int* __restrict__ dst, int E) {
    int e = blockIdx.x * blockDim.x + threadIdx.x;
    if (e >= E) return;
    int d = dst[e];
    int pos = g_rowptr[d] + atomicAdd(&g_cnt2[d], 1);
    g_csr[pos] = src[e];
}

// ---------------- GEMM: C[n,128] = A'[n,128] @ W[128,128] --------------------
// (R2 proven scalar version: ~97% of scalar FFMA roofline)
// 64 rows x 128 cols per block, 256 threads, each thread 8 rows x 4 cols.
__global__ void __launch_bounds__(256) k_gemm(const float* __restrict__ A,
                                              const float* __restrict__ W,
                                              float* __restrict__ C, int n,
                                              int fuseBN) {
    __shared__ float sX[64][DD];   // 32KB
    __shared__ float sW[32][DD];   // 16KB
    const int tid = threadIdx.x;
    const int row0 = blockIdx.x * 64;

    const float4* A4 = (const float4*)A;
    float4* sX4 = (float4*)&sX[0][0];
#pragma unroll
    for (int i = 0; i < 8; i++) {
        int idx = tid + i * 256;            // 0..2047
        int r = idx >> 5, c = idx & 31;
        int gr = row0 + r;
        float4 v = (gr < n) ? A4[(size_t)gr * 32 + c]
                            : make_float4(0.f, 0.f, 0.f, 0.f);
        if (fuseBN) {
            float4 sa = ((const float4*)g_sA)[c];
            float4 sb = ((const float4*)g_sB)[c];
            v.x = fmaxf(fmaf(v.x, sa.x, sb.x), 0.f);
            v.y = fmaxf(fmaf(v.y, sa.y, sb.y), 0.f);
            v.z = fmaxf(fmaf(v.z, sa.z, sb.z), 0.f);
            v.w = fmaxf(fmaf(v.w, sa.w, sb.w), 0.f);
        }
        sX4[idx] = v;
    }

    const int col4 = tid & 31;   // owns cols [4*col4, 4*col4+3]
    const int rg   = tid >> 5;   // row group 0..7 -> rows rg*8..rg*8+7
    float4 acc[8];
#pragma unroll
    for (int j = 0; j < 8; j++) acc[j] = make_float4(0.f, 0.f, 0.f, 0.f);

    const float4* W4 = (const float4*)W;
    float4* sW4 = (float4*)&sW[0][0];
    for (int kc = 0; kc < 4; kc++) {
        __syncthreads();
#pragma unroll
        for (int i = 0; i < 4; i++)
            sW4[tid + i * 256] = W4[(size_t)kc * 1024 + tid + i * 256];
        __syncthreads();
#pragma unroll 4
        for (int kk = 0; kk < 32; kk++) {
            int k = kc * 32 + kk;
            float4 w = *(const float4*)&sW[kk][col4 * 4];
#pragma unroll
            for (int j = 0; j < 8; j++) {
                float xv = sX[rg * 8 + j][k];
                acc[j].x = fmaf(xv, w.x, acc[j].x);
                acc[j].y = fmaf(xv, w.y, acc[j].y);
                acc[j].z = fmaf(xv, w.z, acc[j].z);
                acc[j].w = fmaf(xv, w.w, acc[j].w);
            }
        }
    }
#pragma unroll
    for (int j = 0; j < 8; j++) {
        int gr = row0 + rg * 8 + j;
        if (gr < n) ((float4*)C)[(size_t)gr * 32 + col4] = acc[j];
    }
}

// ---------------- CSR gather: one warp per destination node ------------------
__global__ void __launch_bounds__(256) k_gather(const float* __restrict__ hw,
                                                const float* __restrict__ bias,
                                                const float* __restrict__ agg,
                                                float* __restrict__ outbuf,
                                                int n, int skip) {
    int d = (blockIdx.x * blockDim.x + threadIdx.x) >> 5;
    int lane = threadIdx.x & 31;
    if (d >= n) return;

    const float4* hw4 = (const float4*)hw;
    float invd = g_dis[d];
    float sw = invd * invd;

    float4 acc = ((const float4*)bias)[lane];
    float4 hd = hw4[(size_t)d * 32 + lane];
    acc.x = fmaf(hd.x, sw, acc.x);
    acc.y = fmaf(hd.y, sw, acc.y);
    acc.z = fmaf(hd.z, sw, acc.z);
    acc.w = fmaf(hd.w, sw, acc.w);
    if (skip) {
        float4 a  = ((const float4*)agg)[(size_t)d * 32 + lane];
        float4 sa = ((const float4*)g_sA)[lane];
        float4 sb = ((const float4*)g_sB)[lane];
        acc.x += fmaxf(fmaf(a.x, sa.x, sb.x), 0.f);
        acc.y += fmaxf(fmaf(a.y, sa.y, sb.y), 0.f);
        acc.z += fmaxf(fmaf(a.z, sa.z, sb.z), 0.f);
        acc.w += fmaxf(fmaf(a.w, sa.w, sb.w), 0.f);
    }

    int j   = g_rowptr[d];
    int end = g_rowptr[d + 1];
    for (; j + 3 < end; j += 4) {
        int s0 = g_csr[j],     s1 = g_csr[j + 1];
        int s2 = g_csr[j + 2], s3 = g_csr[j + 3];
        float w0 = g_dis[s0] * invd, w1 = g_dis[s1] * invd;
        float w2 = g_dis[s2] * invd, w3 = g_dis[s3] * invd;
        float4 v0 = hw4[(size_t)s0 * 32 + lane];
        float4 v1 = hw4[(size_t)s1 * 32 + lane];
        float4 v2 = hw4[(size_t)s2 * 32 + lane];
        float4 v3 = hw4[(size_t)s3 * 32 + lane];
        acc.x = fmaf(v0.x, w0, fmaf(v1.x, w1, fmaf(v2.x, w2, fmaf(v3.x, w3, acc.x))));
        acc.y = fmaf(v0.y, w0, fmaf(v1.y, w1, fmaf(v2.y, w2, fmaf(v3.y, w3, acc.y))));
        acc.z = fmaf(v0.z, w0, fmaf(v1.z, w1, fmaf(v2.z, w2, fmaf(v3.z, w3, acc.z))));
        acc.w = fmaf(v0.w, w0, fmaf(v1.w, w1, fmaf(v2.w, w2, fmaf(v3.w, w3, acc.w))));
    }
    for (; j < end; ++j) {
        int s = g_csr[j];
        float w = g_dis[s] * invd;
        float4 v = hw4[(size_t)s * 32 + lane];
        acc.x = fmaf(v.x, w, acc.x);
        acc.y = fmaf(v.y, w, acc.y);
        acc.z = fmaf(v.z, w, acc.z);
        acc.w = fmaf(v.w, w, acc.w);
    }
    ((float4*)outbuf)[(size_t)d * 32 + lane] = acc;
}

// ---------------- BN column stats: sum & sumsq over rows ---------------------
__global__ void k_bnstats(const float* __restrict__ agg, int n) {
    int c = threadIdx.x;  // 128 threads
    float s = 0.f, sq = 0.f;
    for (int r = blockIdx.x; r < n; r += gridDim.x) {
        float v = agg[(size_t)r * DD + c];
        s += v;
        sq = fmaf(v, v, sq);
    }
    atomicAdd(&g_bn[c], s);
    atomicAdd(&g_bn[DD + c], sq);
}

__global__ void k_bnfinal(const float* __restrict__ gamma,
                          const float* __restrict__ beta, float inv_n) {
    int c = threadIdx.x;
    float mu = g_bn[c] * inv_n;
    float var = g_bn[DD + c] * inv_n - mu * mu;
    float rstd = rsqrtf(var + 1e-5f);
    float a = gamma[c] * rstd;
    g_sA[c] = a;
    g_sB[c] = beta[c] - mu * a;
}

// ============================================================================
extern "C" void kernel_launch(void* const* d_in, const int* in_sizes, int n_in,
                              void* d_out, int out_size) {
    const float* x     = (const float*)d_in[0];
    const int*   ei    = (const int*)d_in[1];     // int32 edge_index
    const float* W1    = (const float*)d_in[2];
    const float* b1    = (const float*)d_in[3];
    const float* W2    = (const float*)d_in[4];
    const float* b2    = (const float*)d_in[5];
    const float* gamma = (const float*)d_in[6];
    const float* beta  = (const float*)d_in[7];
    float*       out   = (float*)d_out;

    const int n = in_sizes[0] / DD;
    const int E = in_sizes[1] / 2;
    const int* src = ei;
    const int* dst = ei + E;

    static int inited = 0;
    static cudaStream_t s2;
    static cudaEvent_t evFork, evJoin;
    static void *p_cnt, *p_cnt2, *p_bn, *p_hw, *p_agg;
    if (!inited) {
        cudaStreamCreateWithFlags(&s2, cudaStreamNonBlocking);
        cudaEventCreateWithFlags(&evFork, cudaEventDisableTiming);
        cudaEventCreateWithFlags(&evJoin, cudaEventDisableTiming);
        cudaGetSymbolAddress(&p_cnt,  g_cnt);
        cudaGetSymbolAddress(&p_cnt2, g_cnt2);
        cudaGetSymbolAddress(&p_bn,   g_bn);
        cudaGetSymbolAddress(&p_hw,   g_hw);
        cudaGetSymbolAddress(&p_agg,  g_agg);
        inited = 1;
    }
    float* hw  = (float*)p_hw;
    float* agg = (float*)p_agg;

    const int TB = 256;
    const int n_grid    = (n + TB - 1) / TB;
    const int e_grid    = (E + TB - 1) / TB;
    const int gemm_grid = (n + 63) / 64;
    const int gat_grid  = (n * 32 + TB - 1) / TB;   // warp per node

    // ---- fork: CSR build on s2, overlapped with GEMM1 on the main stream ----
    cudaEventRecord(evFork, 0);
    cudaStreamWaitEvent(s2, evFork, 0);
    cudaMemsetAsync(p_cnt,  0, (size_t)n * 4, s2);
    cudaMemsetAsync(p_cnt2, 0, (size_t)n * 4, s2);
    cudaMemsetAsync(p_bn,   0, 2 * DD * 4, s2);
    k_deg  <<<e_grid, TB, 0, s2>>>(dst, E);
    k_scan1<<<n_grid, TB, 0, s2>>>(n);
    k_scan2<<<1,      TB, 0, s2>>>(n_grid, n);
    k_scan3<<<n_grid, TB, 0, s2>>>(n);
    k_fill <<<e_grid, TB, 0, s2>>>(src, dst, E);
    cudaEventRecord(evJoin, s2);

    // ---- layer 1 (main stream) ----
    k_gemm<<<gemm_grid, TB>>>(x, W1, hw, n, 0);
    cudaStreamWaitEvent(0, evJoin, 0);   // join CSR before gather
    k_gather<<<gat_grid, TB>>>(hw, b1, nullptr, agg, n, 0);
    k_bnstats<<<512, DD>>>(agg, n);
    k_bnfinal<<<1, DD>>>(gamma, beta, 1.0f / (float)n);

    // ---- layer 2: conv on relu(BN(agg)) on the fly; out = h1 + h2 ----
    k_gemm<<<gemm_grid, TB>>>(agg, W2, hw, n, 1);
    k_gather<<<gat_grid, TB>>>(hw, b2, agg, out, n, 1);
}